// round 1
// baseline (speedup 1.0000x reference)
#include <cuda_runtime.h>
#include <math.h>

// Problem constants
#define Bb    8
#define Ll    2048
#define Vv    51919
#define Ee    100
#define Ff    256
#define KW    9
#define Yy    8921
#define YPAD  8960      // 140 * 64
#define YTILES 140
#define HS    260       // padded smem row stride (floats) for 256-wide rows

// Device scratch (no cudaMalloc allowed)
__device__ float g_wT[Ee*KW*Ff];                    // conv weights transposed: [(e*K+k)][f]
__device__ float g_h[(size_t)Bb*Ll*Ff];             // conv output h: [b][l][f]
__device__ float g_sc[146800640];                   // scores / exp scratch: [b][ypad][l] (8*8960*2048)

// ---------------------------------------------------------------------------
// K0: transpose conv_w [F,E,K] -> g_wT [(E*K), F]
// ---------------------------------------------------------------------------
__global__ void k_transpose(const float* __restrict__ w)
{
    int idx = blockIdx.x * 256 + threadIdx.x;
    if (idx < Ff*Ee*KW) {
        int f = idx / (Ee*KW);
        int r = idx - f*(Ee*KW);
        g_wT[r*Ff + f] = w[idx];
    }
}

// ---------------------------------------------------------------------------
// K1: embedding gather + conv1d(K=9, same pad) + bias + tanh -> g_h [b][l][f]
// One block = 16 output positions for one batch; 256 threads = one f each.
// ---------------------------------------------------------------------------
__global__ __launch_bounds__(256) void k_conv(const int* __restrict__ x,
                                              const float* __restrict__ embW,
                                              const float* __restrict__ convb)
{
    __shared__ int   toks[24];
    __shared__ float semb[24][Ee];

    int tid = threadIdx.x;
    int b   = blockIdx.y;
    int l0  = blockIdx.x * 16;

    if (tid < 24) {
        int l = l0 - 4 + tid;
        toks[tid] = (l >= 0 && l < Ll) ? x[b*Ll + l] : -1;
    }
    __syncthreads();

    for (int idx = tid; idx < 24*Ee; idx += 256) {
        int t = idx / Ee;
        int c = idx - t*Ee;
        int tok = toks[t];
        semb[t][c] = (tok >= 0) ? embW[(size_t)tok*Ee + c] : 0.f;
    }
    __syncthreads();

    int f = tid;
    float acc[16];
#pragma unroll
    for (int j = 0; j < 16; j++) acc[j] = 0.f;

    for (int e = 0; e < Ee; e++) {
        float r[24];
#pragma unroll
        for (int t = 0; t < 24; t++) r[t] = semb[t][e];
#pragma unroll
        for (int k = 0; k < KW; k++) {
            float w = g_wT[(e*KW + k)*Ff + f];
#pragma unroll
            for (int j = 0; j < 16; j++)
                acc[j] = fmaf(w, r[j + k], acc[j]);
        }
    }

    float bias = convb[f];
    float* hp = g_h + ((size_t)b*Ll + l0)*Ff + f;
#pragma unroll
    for (int j = 0; j < 16; j++)
        hp[(size_t)j*Ff] = tanhf(acc[j] + bias);
}

// ---------------------------------------------------------------------------
// K2: fused per (batch, 64-label tile):
//   pass A: scores = U * h^T  (store to g_sc, track row max)
//   pass B: e = exp(s - max) (store back to g_sc), rowsum, m += e * h
//   finalize: yhat, alpha = e / rowsum -> d_out
// Thread map: tid = ty*16 + tl; micro-tile 4y x 4l (pass A), 4y x 16f (pass B)
// ---------------------------------------------------------------------------
#define SM_FLOATS (64*HS + 64*HS + 64*64 + 64*16 + 64 + 64)
#define SM_BYTES  (SM_FLOATS * 4)

__global__ __launch_bounds__(256) void k_attn(const float* __restrict__ Uw,
                                              const float* __restrict__ fw,
                                              const float* __restrict__ fb,
                                              float* __restrict__ out)
{
    extern __shared__ float sm[];
    float* Usm     = sm;                    // [64][HS]
    float* hsm     = Usm + 64*HS;           // [64][HS]
    float* esm     = hsm + 64*HS;           // [64][64]
    float* red     = esm + 64*64;           // [64][16]
    float* rowmaxs = red + 64*16;           // [64]
    float* rowsums = rowmaxs + 64;          // [64]

    int tid = threadIdx.x;
    int ty  = tid >> 4;       // 0..15 -> 4 y's each
    int tl  = tid & 15;       // 0..15 -> 4 l's each (pass A) / 16 f's (pass B)
    int b   = blockIdx.y;
    int yt  = blockIdx.x;
    int ybase = yt * 64;

    // Load U tile (zero-fill beyond Y)
    for (int idx = tid; idx < 64*256; idx += 256) {
        int r = idx >> 8, c = idx & 255;
        int gy = ybase + r;
        Usm[r*HS + c] = (gy < Yy) ? Uw[(size_t)gy*Ff + c] : 0.f;
    }

    float rmax[4];
#pragma unroll
    for (int i = 0; i < 4; i++) rmax[i] = -1e30f;
    __syncthreads();

    const float* hbase = g_h + (size_t)b*Ll*Ff;
    float* scb = g_sc + ((size_t)b*YPAD + ybase)*Ll;

    // ---------------- pass A: scores GEMM ----------------
    for (int lc = 0; lc < Ll/64; lc++) {
        const float4* hp4 = (const float4*)(hbase + (size_t)lc*64*Ff);
        for (int idx = tid; idx < 64*64; idx += 256) {
            int r = idx >> 6, c4 = idx & 63;
            *((float4*)(hsm + r*HS) + c4) = hp4[r*64 + c4];
        }
        __syncthreads();

        float acc[4][4];
#pragma unroll
        for (int i = 0; i < 4; i++)
#pragma unroll
            for (int j = 0; j < 4; j++) acc[i][j] = 0.f;

#pragma unroll 4
        for (int k = 0; k < 256; k += 4) {
            float4 av[4], bv[4];
#pragma unroll
            for (int yi = 0; yi < 4; yi++)
                av[yi] = *(const float4*)&Usm[(ty*4 + yi)*HS + k];
#pragma unroll
            for (int li = 0; li < 4; li++)
                bv[li] = *(const float4*)&hsm[(tl*4 + li)*HS + k];
#pragma unroll
            for (int yi = 0; yi < 4; yi++)
#pragma unroll
                for (int li = 0; li < 4; li++) {
                    acc[yi][li] = fmaf(av[yi].x, bv[li].x, acc[yi][li]);
                    acc[yi][li] = fmaf(av[yi].y, bv[li].y, acc[yi][li]);
                    acc[yi][li] = fmaf(av[yi].z, bv[li].z, acc[yi][li]);
                    acc[yi][li] = fmaf(av[yi].w, bv[li].w, acc[yi][li]);
                }
        }

#pragma unroll
        for (int yi = 0; yi < 4; yi++) {
            float4 v = make_float4(acc[yi][0], acc[yi][1], acc[yi][2], acc[yi][3]);
            *(float4*)&scb[(size_t)(ty*4 + yi)*Ll + lc*64 + tl*4] = v;
            rmax[yi] = fmaxf(rmax[yi], fmaxf(fmaxf(v.x, v.y), fmaxf(v.z, v.w)));
        }
        __syncthreads();
    }

    // row max reduce across the 16 tl threads per y
#pragma unroll
    for (int yi = 0; yi < 4; yi++) red[(ty*4 + yi)*16 + tl] = rmax[yi];
    __syncthreads();
    if (tid < 64) {
        float mx = -1e30f;
#pragma unroll
        for (int i = 0; i < 16; i++) mx = fmaxf(mx, red[tid*16 + i]);
        rowmaxs[tid] = mx;
    }
    __syncthreads();

    // ---------------- pass B: exp + rowsum + m GEMM ----------------
    float macc[4][16];
#pragma unroll
    for (int yi = 0; yi < 4; yi++)
#pragma unroll
        for (int fi = 0; fi < 16; fi++) macc[yi][fi] = 0.f;
    float rsum[4] = {0.f, 0.f, 0.f, 0.f};

    for (int lc = 0; lc < Ll/64; lc++) {
        const float4* hp4 = (const float4*)(hbase + (size_t)lc*64*Ff);
        for (int idx = tid; idx < 64*64; idx += 256) {
            int r = idx >> 6, c4 = idx & 63;
            *((float4*)(hsm + r*HS) + c4) = hp4[r*64 + c4];
        }

#pragma unroll
        for (int yi = 0; yi < 4; yi++) {
            int y = ty*4 + yi;
            float mx = rowmaxs[y];
            size_t off = (size_t)y*Ll + lc*64 + tl*4;
            float4 s = *(float4*)&scb[off];
            float4 ev;
            ev.x = __expf(s.x - mx);
            ev.y = __expf(s.y - mx);
            ev.z = __expf(s.z - mx);
            ev.w = __expf(s.w - mx);
            rsum[yi] += ev.x + ev.y + ev.z + ev.w;
            *(float4*)&scb[off] = ev;
            *(float4*)&esm[y*64 + tl*4] = ev;
        }
        __syncthreads();

#pragma unroll 2
        for (int l = 0; l < 64; l++) {
            float evv[4];
#pragma unroll
            for (int yi = 0; yi < 4; yi++) evv[yi] = esm[(ty*4 + yi)*64 + l];
            const float* hr = hsm + l*HS + tl*16;
            float4 h0 = *(const float4*)(hr);
            float4 h1 = *(const float4*)(hr + 4);
            float4 h2 = *(const float4*)(hr + 8);
            float4 h3 = *(const float4*)(hr + 12);
#pragma unroll
            for (int yi = 0; yi < 4; yi++) {
                float e = evv[yi];
                macc[yi][0]  = fmaf(e, h0.x, macc[yi][0]);
                macc[yi][1]  = fmaf(e, h0.y, macc[yi][1]);
                macc[yi][2]  = fmaf(e, h0.z, macc[yi][2]);
                macc[yi][3]  = fmaf(e, h0.w, macc[yi][3]);
                macc[yi][4]  = fmaf(e, h1.x, macc[yi][4]);
                macc[yi][5]  = fmaf(e, h1.y, macc[yi][5]);
                macc[yi][6]  = fmaf(e, h1.z, macc[yi][6]);
                macc[yi][7]  = fmaf(e, h1.w, macc[yi][7]);
                macc[yi][8]  = fmaf(e, h2.x, macc[yi][8]);
                macc[yi][9]  = fmaf(e, h2.y, macc[yi][9]);
                macc[yi][10] = fmaf(e, h2.z, macc[yi][10]);
                macc[yi][11] = fmaf(e, h2.w, macc[yi][11]);
                macc[yi][12] = fmaf(e, h3.x, macc[yi][12]);
                macc[yi][13] = fmaf(e, h3.y, macc[yi][13]);
                macc[yi][14] = fmaf(e, h3.z, macc[yi][14]);
                macc[yi][15] = fmaf(e, h3.w, macc[yi][15]);
            }
        }
        __syncthreads();
    }

    // rowsum reduce
#pragma unroll
    for (int yi = 0; yi < 4; yi++) red[(ty*4 + yi)*16 + tl] = rsum[yi];
    __syncthreads();
    if (tid < 64) {
        float s = 0.f;
#pragma unroll
        for (int i = 0; i < 16; i++) s += red[tid*16 + i];
        rowsums[tid] = s;
    }
    __syncthreads();

    // ---------------- yhat ----------------
#pragma unroll
    for (int yi = 0; yi < 4; yi++) {
        int y = ty*4 + yi;
        int gy = ybase + y;
        float p = 0.f;
        if (gy < Yy) {
            const float* fwr = fw + (size_t)gy*Ff + tl*16;
#pragma unroll
            for (int fi = 0; fi < 16; fi++)
                p = fmaf(fwr[fi], macc[yi][fi], p);
        }
        red[y*16 + tl] = p;
    }
    __syncthreads();
    if (tid < 64) {
        int gy = ybase + tid;
        if (gy < Yy) {
            float s = 0.f;
#pragma unroll
            for (int i = 0; i < 16; i++) s += red[tid*16 + i];
            out[(size_t)b*Yy + gy] = s / rowsums[tid] + fb[gy];
        }
    }
    __syncthreads();

    // ---------------- alpha output ----------------
    // out layout: yhat [B*Y], loss [1], alpha [B][Y][L]
    float* alpha = out + (size_t)Bb*Yy + 1;
    for (int idx = tid; idx < 64*Ll; idx += 256) {
        int y = idx >> 11;          // /2048
        int l = idx & 2047;
        int gy = ybase + y;
        if (gy < Yy) {
            float inv = 1.f / rowsums[y];
            alpha[(size_t)((size_t)b*Yy + gy)*Ll + l] = scb[(size_t)y*Ll + l] * inv;
        }
    }
}

// ---------------------------------------------------------------------------
// K3: BCE-with-logits mean loss over yhat (already in d_out) and target
// ---------------------------------------------------------------------------
__global__ void k_loss(const float* __restrict__ target, float* __restrict__ out)
{
    __shared__ float red[256];
    int tid = threadIdx.x;
    float s = 0.f;
    for (int i = tid; i < Bb*Yy; i += 256) {
        float yh = out[i];
        float t  = target[i];
        s += fmaxf(yh, 0.f) - yh*t + log1pf(__expf(-fabsf(yh)));
    }
    red[tid] = s;
    __syncthreads();
    for (int st = 128; st > 0; st >>= 1) {
        if (tid < st) red[tid] += red[tid + st];
        __syncthreads();
    }
    if (tid == 0) out[Bb*Yy] = red[0] / (float)(Bb*Yy);
}

// ---------------------------------------------------------------------------
extern "C" void kernel_launch(void* const* d_in, const int* in_sizes, int n_in,
                              void* d_out, int out_size)
{
    const int*   x      = (const int*)d_in[0];
    const float* target = (const float*)d_in[1];
    const float* embW   = (const float*)d_in[2];
    const float* convw  = (const float*)d_in[3];
    const float* convb  = (const float*)d_in[4];
    const float* Uw     = (const float*)d_in[5];
    const float* fw     = (const float*)d_in[6];
    const float* fb     = (const float*)d_in[7];
    float* out = (float*)d_out;

    cudaFuncSetAttribute(k_attn, cudaFuncAttributeMaxDynamicSharedMemorySize, SM_BYTES);

    k_transpose<<<(Ff*Ee*KW + 255)/256, 256>>>(convw);
    k_conv<<<dim3(Ll/16, Bb), 256>>>(x, embW, convb);
    k_attn<<<dim3(YTILES, Bb), 256, SM_BYTES>>>(Uw, fw, fb, out);
    k_loss<<<1, 256>>>(target, out);
}

// round 3
// speedup vs baseline: 1.0936x; 1.0936x over previous
#include <cuda_runtime.h>
#include <math.h>

// Problem constants
#define Bb    8
#define Ll    2048
#define Vv    51919
#define Ee    100
#define Ff    256
#define KW    9
#define Yy    8921
#define YPAD  8960      // 140 * 64
#define YTILES 140
#define HS    260       // padded smem row stride (floats) for 256-wide rows

// Device scratch (no cudaMalloc allowed)
__device__ float g_wT[Ee*KW*Ff];          // conv weights transposed: [(e*K+k)][f]
__device__ float g_h[(size_t)Bb*Ll*Ff];   // conv output h: [b][l][f]
__device__ float g_part[256];             // loss partials

// ---------------------------------------------------------------------------
// K0: transpose conv_w [F,E,K] -> g_wT [(E*K), F]
// ---------------------------------------------------------------------------
__global__ void k_transpose(const float* __restrict__ w)
{
    int idx = blockIdx.x * 256 + threadIdx.x;
    if (idx < Ff*Ee*KW) {
        int f = idx / (Ee*KW);
        int r = idx - f*(Ee*KW);
        g_wT[r*Ff + f] = w[idx];
    }
}

// ---------------------------------------------------------------------------
// K1: embedding gather + conv1d(K=9, same pad) + bias + tanh -> g_h [b][l][f]
// ---------------------------------------------------------------------------
__global__ __launch_bounds__(256) void k_conv(const int* __restrict__ x,
                                              const float* __restrict__ embW,
                                              const float* __restrict__ convb)
{
    __shared__ int   toks[24];
    __shared__ float semb[24][Ee];

    int tid = threadIdx.x;
    int b   = blockIdx.y;
    int l0  = blockIdx.x * 16;

    if (tid < 24) {
        int l = l0 - 4 + tid;
        toks[tid] = (l >= 0 && l < Ll) ? x[b*Ll + l] : -1;
    }
    __syncthreads();

    for (int idx = tid; idx < 24*Ee; idx += 256) {
        int t = idx / Ee;
        int c = idx - t*Ee;
        int tok = toks[t];
        semb[t][c] = (tok >= 0) ? embW[(size_t)tok*Ee + c] : 0.f;
    }
    __syncthreads();

    int f = tid;
    float acc[16];
#pragma unroll
    for (int j = 0; j < 16; j++) acc[j] = 0.f;

    for (int e = 0; e < Ee; e++) {
        float r[24];
#pragma unroll
        for (int t = 0; t < 24; t++) r[t] = semb[t][e];
#pragma unroll
        for (int k = 0; k < KW; k++) {
            float w = g_wT[(e*KW + k)*Ff + f];
#pragma unroll
            for (int j = 0; j < 16; j++)
                acc[j] = fmaf(w, r[j + k], acc[j]);
        }
    }

    float bias = convb[f];
    float* hp = g_h + ((size_t)b*Ll + l0)*Ff + f;
#pragma unroll
    for (int j = 0; j < 16; j++)
        hp[(size_t)j*Ff] = tanhf(acc[j] + bias);
}

// ---------------------------------------------------------------------------
// K2: FUSED per (batch, 64-label tile), single pass over L:
//   s = U*h^T (registers) -> e = exp(s) (unstabilized; |s| small, safe in fp32)
//   -> rsum += e, m += e*h, stream unnormalized e to alpha slot in d_out
//   then yhat, then alpha *= 1/Z rescale (reads mostly L2)
// NOTE: alpha region of d_out starts at element B*Y+1 (NOT 16B-aligned!)
//       -> all global accesses there must be scalar (4B) but coalesced.
// ---------------------------------------------------------------------------
#define SM_FLOATS (64*HS + 64*HS + 64*64 + 64*16 + 64)
#define SM_BYTES  (SM_FLOATS * 4)

__global__ __launch_bounds__(256) void k_attn(const float* __restrict__ Uw,
                                              const float* __restrict__ fw,
                                              const float* __restrict__ fb,
                                              float* __restrict__ out)
{
    extern __shared__ float sm[];
    float* Usm     = sm;                    // [64][HS]
    float* hsm     = Usm + 64*HS;           // [64][HS]
    float* esm     = hsm + 64*HS;           // [64][64]
    float* red     = esm + 64*64;           // [64][16]
    float* rowsums = red + 64*16;           // [64]

    int tid = threadIdx.x;
    int ty  = tid >> 4;       // 0..15 -> 4 y's each
    int tl  = tid & 15;       // 0..15 -> 4 l's (s phase) / 16 f's (m phase)
    int b   = blockIdx.y;
    int yt  = blockIdx.x;
    int ybase = yt * 64;

    // Load U tile (zero-fill beyond Y)
    for (int idx = tid; idx < 64*256; idx += 256) {
        int r = idx >> 8, c = idx & 255;
        int gy = ybase + r;
        Usm[r*HS + c] = (gy < Yy) ? Uw[(size_t)gy*Ff + c] : 0.f;
    }

    float macc[4][16];
#pragma unroll
    for (int yi = 0; yi < 4; yi++)
#pragma unroll
        for (int fi = 0; fi < 16; fi++) macc[yi][fi] = 0.f;
    float rsum[4] = {0.f, 0.f, 0.f, 0.f};
    __syncthreads();

    const float* hbase = g_h + (size_t)b*Ll*Ff;
    // out layout: yhat [B*Y], loss [1], alpha [B][Y][L]
    float* alpha = out + (size_t)Bb*Yy + 1;
    float* ablk  = alpha + ((size_t)b*Yy + ybase)*Ll;

    for (int lc = 0; lc < Ll/64; lc++) {
        // load h tile [64 l][256 f]
        const float4* hp4 = (const float4*)(hbase + (size_t)lc*64*Ff);
        for (int idx = tid; idx < 64*64; idx += 256) {
            int r = idx >> 6, c4 = idx & 63;
            *((float4*)(hsm + r*HS) + c4) = hp4[r*64 + c4];
        }
        __syncthreads();

        // ---- s-GEMM 4y x 4l ----
        float acc[4][4];
#pragma unroll
        for (int i = 0; i < 4; i++)
#pragma unroll
            for (int j = 0; j < 4; j++) acc[i][j] = 0.f;

#pragma unroll 4
        for (int k = 0; k < 256; k += 4) {
            float4 av[4], bv[4];
#pragma unroll
            for (int yi = 0; yi < 4; yi++)
                av[yi] = *(const float4*)&Usm[(ty*4 + yi)*HS + k];
#pragma unroll
            for (int li = 0; li < 4; li++)
                bv[li] = *(const float4*)&hsm[(tl*4 + li)*HS + k];
#pragma unroll
            for (int yi = 0; yi < 4; yi++)
#pragma unroll
                for (int li = 0; li < 4; li++) {
                    acc[yi][li] = fmaf(av[yi].x, bv[li].x, acc[yi][li]);
                    acc[yi][li] = fmaf(av[yi].y, bv[li].y, acc[yi][li]);
                    acc[yi][li] = fmaf(av[yi].z, bv[li].z, acc[yi][li]);
                    acc[yi][li] = fmaf(av[yi].w, bv[li].w, acc[yi][li]);
                }
        }

        // ---- e = exp(s); rowsum; stash to esm (smem, aligned float4) ----
#pragma unroll
        for (int yi = 0; yi < 4; yi++) {
            int y = ty*4 + yi;
            float4 ev;
            ev.x = __expf(acc[yi][0]);
            ev.y = __expf(acc[yi][1]);
            ev.z = __expf(acc[yi][2]);
            ev.w = __expf(acc[yi][3]);
            rsum[yi] += ev.x + ev.y + ev.z + ev.w;
            *(float4*)&esm[y*64 + tl*4] = ev;
        }
        __syncthreads();

        // ---- coalesced SCALAR stream of e to gmem (alpha base misaligned) ----
        for (int idx = tid; idx < 64*64; idx += 256) {
            int y = idx >> 6, l = idx & 63;
            if (ybase + y < Yy)
                ablk[(size_t)y*Ll + lc*64 + l] = esm[idx];
        }

        // ---- m-GEMM: macc[y][f] += e[y][l] * h[l][f] ----
#pragma unroll 2
        for (int l = 0; l < 64; l++) {
            float evv[4];
#pragma unroll
            for (int yi = 0; yi < 4; yi++) evv[yi] = esm[(ty*4 + yi)*64 + l];
            const float* hr = hsm + l*HS + tl*16;
            float4 h0 = *(const float4*)(hr);
            float4 h1 = *(const float4*)(hr + 4);
            float4 h2 = *(const float4*)(hr + 8);
            float4 h3 = *(const float4*)(hr + 12);
#pragma unroll
            for (int yi = 0; yi < 4; yi++) {
                float e = evv[yi];
                macc[yi][0]  = fmaf(e, h0.x, macc[yi][0]);
                macc[yi][1]  = fmaf(e, h0.y, macc[yi][1]);
                macc[yi][2]  = fmaf(e, h0.z, macc[yi][2]);
                macc[yi][3]  = fmaf(e, h0.w, macc[yi][3]);
                macc[yi][4]  = fmaf(e, h1.x, macc[yi][4]);
                macc[yi][5]  = fmaf(e, h1.y, macc[yi][5]);
                macc[yi][6]  = fmaf(e, h1.z, macc[yi][6]);
                macc[yi][7]  = fmaf(e, h1.w, macc[yi][7]);
                macc[yi][8]  = fmaf(e, h2.x, macc[yi][8]);
                macc[yi][9]  = fmaf(e, h2.y, macc[yi][9]);
                macc[yi][10] = fmaf(e, h2.z, macc[yi][10]);
                macc[yi][11] = fmaf(e, h2.w, macc[yi][11]);
                macc[yi][12] = fmaf(e, h3.x, macc[yi][12]);
                macc[yi][13] = fmaf(e, h3.y, macc[yi][13]);
                macc[yi][14] = fmaf(e, h3.z, macc[yi][14]);
                macc[yi][15] = fmaf(e, h3.w, macc[yi][15]);
            }
        }
        __syncthreads();
    }

    // rowsum reduce across the 16 tl threads per y
#pragma unroll
    for (int yi = 0; yi < 4; yi++) red[(ty*4 + yi)*16 + tl] = rsum[yi];
    __syncthreads();
    if (tid < 64) {
        float s = 0.f;
#pragma unroll
        for (int i = 0; i < 16; i++) s += red[tid*16 + i];
        rowsums[tid] = s;
    }
    __syncthreads();

    // ---------------- yhat ----------------
#pragma unroll
    for (int yi = 0; yi < 4; yi++) {
        int y = ty*4 + yi;
        int gy = ybase + y;
        float p = 0.f;
        if (gy < Yy) {
            const float* fwr = fw + (size_t)gy*Ff + tl*16;
#pragma unroll
            for (int fi = 0; fi < 16; fi++)
                p = fmaf(fwr[fi], macc[yi][fi], p);
        }
        red[y*16 + tl] = p;
    }
    __syncthreads();
    if (tid < 64) {
        int gy = ybase + tid;
        if (gy < Yy) {
            float s = 0.f;
#pragma unroll
            for (int i = 0; i < 16; i++) s += red[tid*16 + i];
            out[(size_t)b*Yy + gy] = s / rowsums[tid] + fb[gy];
        }
    }
    __syncthreads();

    // ---------------- alpha rescale: alpha = e / Z (scalar, coalesced) -------
    for (int y = 0; y < 64; y++) {
        int gy = ybase + y;
        if (gy >= Yy) break;
        float inv = 1.f / rowsums[y];
        float* row = ablk + (size_t)y*Ll;
        for (int l = tid; l < Ll; l += 256)
            row[l] *= inv;
    }
}

// ---------------------------------------------------------------------------
// K3: BCE loss, two-stage deterministic reduction
// ---------------------------------------------------------------------------
__global__ void k_loss1(const float* __restrict__ target, const float* __restrict__ out)
{
    __shared__ float red[256];
    int tid = threadIdx.x;
    float s = 0.f;
    for (int i = blockIdx.x*256 + tid; i < Bb*Yy; i += gridDim.x*256) {
        float yh = out[i];
        float t  = target[i];
        s += fmaxf(yh, 0.f) - yh*t + log1pf(__expf(-fabsf(yh)));
    }
    red[tid] = s;
    __syncthreads();
    for (int st = 128; st > 0; st >>= 1) {
        if (tid < st) red[tid] += red[tid + st];
        __syncthreads();
    }
    if (tid == 0) g_part[blockIdx.x] = red[0];
}

__global__ void k_loss2(float* __restrict__ out)
{
    __shared__ float red[128];
    int tid = threadIdx.x;
    red[tid] = (tid < 70) ? g_part[tid] : 0.f;
    __syncthreads();
    for (int st = 64; st > 0; st >>= 1) {
        if (tid < st) red[tid] += red[tid + st];
        __syncthreads();
    }
    if (tid == 0) out[Bb*Yy] = red[0] / (float)(Bb*Yy);
}

// ---------------------------------------------------------------------------
extern "C" void kernel_launch(void* const* d_in, const int* in_sizes, int n_in,
                              void* d_out, int out_size)
{
    const int*   x      = (const int*)d_in[0];
    const float* target = (const float*)d_in[1];
    const float* embW   = (const float*)d_in[2];
    const float* convw  = (const float*)d_in[3];
    const float* convb  = (const float*)d_in[4];
    const float* Uw     = (const float*)d_in[5];
    const float* fw     = (const float*)d_in[6];
    const float* fb     = (const float*)d_in[7];
    float* out = (float*)d_out;

    cudaFuncSetAttribute(k_attn, cudaFuncAttributeMaxDynamicSharedMemorySize, SM_BYTES);

    k_transpose<<<(Ff*Ee*KW + 255)/256, 256>>>(convw);
    k_conv<<<dim3(Ll/16, Bb), 256>>>(x, embW, convb);
    k_attn<<<dim3(YTILES, Bb), 256, SM_BYTES>>>(Uw, fw, fb, out);
    k_loss1<<<70, 256>>>(target, out);
    k_loss2<<<1, 128>>>(out);
}

// round 4
// speedup vs baseline: 1.5946x; 1.4581x over previous
#include <cuda_runtime.h>
#include <math.h>

// Problem constants
#define Bb    8
#define Ll    2048
#define Vv    51919
#define Ee    100
#define Ff    256
#define KW    9
#define Yy    8921
#define YTILES 140
#define US    260       // Usm row stride (floats): mult of 4 (alignment), rows+4 -> distinct bank groups

// Device scratch (no cudaMalloc allowed)
__device__ float g_wT[Ee*KW*Ff];          // conv weights transposed: [(e*K+k)][f]
__device__ float g_h[(size_t)Bb*Ll*Ff];   // conv output h: [b][l][f]
__device__ float g_part[256];             // loss partials

// ---------------------------------------------------------------------------
// K0: transpose conv_w [F,E,K] -> g_wT [(E*K), F]
// ---------------------------------------------------------------------------
__global__ void k_transpose(const float* __restrict__ w)
{
    int idx = blockIdx.x * 256 + threadIdx.x;
    if (idx < Ff*Ee*KW) {
        int f = idx / (Ee*KW);
        int r = idx - f*(Ee*KW);
        g_wT[r*Ff + f] = w[idx];
    }
}

// ---------------------------------------------------------------------------
// K1: embedding gather + conv1d(K=9, same pad) + bias + tanh -> g_h [b][l][f]
// ---------------------------------------------------------------------------
__global__ __launch_bounds__(256) void k_conv(const int* __restrict__ x,
                                              const float* __restrict__ embW,
                                              const float* __restrict__ convb)
{
    __shared__ int   toks[24];
    __shared__ float semb[24][Ee];

    int tid = threadIdx.x;
    int b   = blockIdx.y;
    int l0  = blockIdx.x * 16;

    if (tid < 24) {
        int l = l0 - 4 + tid;
        toks[tid] = (l >= 0 && l < Ll) ? x[b*Ll + l] : -1;
    }
    __syncthreads();

    for (int idx = tid; idx < 24*Ee; idx += 256) {
        int t = idx / Ee;
        int c = idx - t*Ee;
        int tok = toks[t];
        semb[t][c] = (tok >= 0) ? embW[(size_t)tok*Ee + c] : 0.f;
    }
    __syncthreads();

    int f = tid;
    float acc[16];
#pragma unroll
    for (int j = 0; j < 16; j++) acc[j] = 0.f;

    for (int e = 0; e < Ee; e++) {
        float r[24];
#pragma unroll
        for (int t = 0; t < 24; t++) r[t] = semb[t][e];
#pragma unroll
        for (int k = 0; k < KW; k++) {
            float w = g_wT[(e*KW + k)*Ff + f];
#pragma unroll
            for (int j = 0; j < 16; j++)
                acc[j] = fmaf(w, r[j + k], acc[j]);
        }
    }

    float bias = convb[f];
    float* hp = g_h + ((size_t)b*Ll + l0)*Ff + f;
#pragma unroll
    for (int j = 0; j < 16; j++)
        hp[(size_t)j*Ff] = tanhf(acc[j] + bias);
}

// ---------------------------------------------------------------------------
// K2: FUSED attention per (batch, 64-label tile), single pass over L.
//   h tile stored as XOR-swizzled float4 slots: slot(r,c4) = r*64 + (c4 ^ ((r>>2)&7))
//   -> conflict-free LDS.128 in both GEMM phases (quarter-warp wavefronts).
//   m-GEMM per-thread f-tile: f = fi*64 + tl*4 + j  (4 x float4 at chunk fi*16+tl)
// NOTE: alpha region of d_out starts at element B*Y+1 (NOT 16B-aligned)
//       -> all global accesses there are scalar (4B) but coalesced.
// ---------------------------------------------------------------------------
#define SM_FLOATS (64*US + 64*256 + 64*64 + 64*16 + 64)
#define SM_BYTES  (SM_FLOATS * 4)

__global__ __launch_bounds__(256) void k_attn(const float* __restrict__ Uw,
                                              const float* __restrict__ fw,
                                              const float* __restrict__ fb,
                                              float* __restrict__ out)
{
    extern __shared__ float sm[];
    float*  Usm     = sm;                    // [64][US]
    float4* hsm4    = (float4*)(sm + 64*US); // [64 rows][64 slots] swizzled
    float*  esm     = sm + 64*US + 64*256;   // [64][64]
    float*  red     = esm + 64*64;           // [64][16]
    float*  rowsums = red + 64*16;           // [64]

    int tid = threadIdx.x;
    int ty  = tid >> 4;       // 0..15 -> 4 y's each
    int tl  = tid & 15;       // 0..15
    int b   = blockIdx.y;
    int ybase = blockIdx.x * 64;

    // Load U tile (zero-fill beyond Y)
    for (int idx = tid; idx < 64*256; idx += 256) {
        int r = idx >> 8, c = idx & 255;
        int gy = ybase + r;
        Usm[r*US + c] = (gy < Yy) ? Uw[(size_t)gy*Ff + c] : 0.f;
    }

    float macc[4][16];
#pragma unroll
    for (int yi = 0; yi < 4; yi++)
#pragma unroll
        for (int fi = 0; fi < 16; fi++) macc[yi][fi] = 0.f;
    float rsum[4] = {0.f, 0.f, 0.f, 0.f};
    __syncthreads();

    const float* hbase = g_h + (size_t)b*Ll*Ff;
    // out layout: yhat [B*Y], loss [1], alpha [B][Y][L]
    float* alpha = out + (size_t)Bb*Yy + 1;
    float* ablk  = alpha + ((size_t)b*Yy + ybase)*Ll;

    for (int lc = 0; lc < Ll/64; lc++) {
        // load h tile [64 l][256 f] with xor swizzle on float4 slots
        const float4* hp4 = (const float4*)(hbase + (size_t)lc*64*Ff);
        for (int idx = tid; idx < 64*64; idx += 256) {
            int r = idx >> 6, c4 = idx & 63;
            hsm4[r*64 + (c4 ^ ((r >> 2) & 7))] = hp4[r*64 + c4];
        }
        __syncthreads();

        // ---- s-GEMM 4y x 4l ----
        float acc[4][4];
#pragma unroll
        for (int i = 0; i < 4; i++)
#pragma unroll
            for (int j = 0; j < 4; j++) acc[i][j] = 0.f;

#pragma unroll 4
        for (int k4 = 0; k4 < 64; k4++) {
            int sw = k4 ^ (tl & 7);     // swizzle term: (tl*4+li)>>2 == tl for li<4
            float4 bv[4];
#pragma unroll
            for (int li = 0; li < 4; li++)
                bv[li] = hsm4[(tl*4 + li)*64 + sw];
            float4 av[4];
#pragma unroll
            for (int yi = 0; yi < 4; yi++)
                av[yi] = *(const float4*)&Usm[(ty*4 + yi)*US + k4*4];
#pragma unroll
            for (int yi = 0; yi < 4; yi++)
#pragma unroll
                for (int li = 0; li < 4; li++) {
                    acc[yi][li] = fmaf(av[yi].x, bv[li].x, acc[yi][li]);
                    acc[yi][li] = fmaf(av[yi].y, bv[li].y, acc[yi][li]);
                    acc[yi][li] = fmaf(av[yi].z, bv[li].z, acc[yi][li]);
                    acc[yi][li] = fmaf(av[yi].w, bv[li].w, acc[yi][li]);
                }
        }

        // ---- e = exp(s); rowsum; stash to esm ----
#pragma unroll
        for (int yi = 0; yi < 4; yi++) {
            int y = ty*4 + yi;
            float4 ev;
            ev.x = __expf(acc[yi][0]);
            ev.y = __expf(acc[yi][1]);
            ev.z = __expf(acc[yi][2]);
            ev.w = __expf(acc[yi][3]);
            rsum[yi] += ev.x + ev.y + ev.z + ev.w;
            *(float4*)&esm[y*64 + tl*4] = ev;
        }
        __syncthreads();

        // ---- coalesced SCALAR stream of e to gmem (alpha base misaligned) ----
        for (int idx = tid; idx < 64*64; idx += 256) {
            int y = idx >> 6, l = idx & 63;
            if (ybase + y < Yy)
                ablk[(size_t)y*Ll + lc*64 + l] = esm[idx];
        }

        // ---- m-GEMM: macc[y][fi*4+j] += e[y][l] * h[l][fi*64+tl*4+j] ----
#pragma unroll 2
        for (int l = 0; l < 64; l++) {
            int x = (l >> 2) & 7;
            const float4* hrow = hsm4 + l*64;
            int t = tl ^ x;
            float4 h0 = hrow[t];
            float4 h1 = hrow[16 + t];
            float4 h2 = hrow[32 + t];
            float4 h3 = hrow[48 + t];
            float evv[4];
#pragma unroll
            for (int yi = 0; yi < 4; yi++) evv[yi] = esm[(ty*4 + yi)*64 + l];
#pragma unroll
            for (int yi = 0; yi < 4; yi++) {
                float e = evv[yi];
                macc[yi][0]  = fmaf(e, h0.x, macc[yi][0]);
                macc[yi][1]  = fmaf(e, h0.y, macc[yi][1]);
                macc[yi][2]  = fmaf(e, h0.z, macc[yi][2]);
                macc[yi][3]  = fmaf(e, h0.w, macc[yi][3]);
                macc[yi][4]  = fmaf(e, h1.x, macc[yi][4]);
                macc[yi][5]  = fmaf(e, h1.y, macc[yi][5]);
                macc[yi][6]  = fmaf(e, h1.z, macc[yi][6]);
                macc[yi][7]  = fmaf(e, h1.w, macc[yi][7]);
                macc[yi][8]  = fmaf(e, h2.x, macc[yi][8]);
                macc[yi][9]  = fmaf(e, h2.y, macc[yi][9]);
                macc[yi][10] = fmaf(e, h2.z, macc[yi][10]);
                macc[yi][11] = fmaf(e, h2.w, macc[yi][11]);
                macc[yi][12] = fmaf(e, h3.x, macc[yi][12]);
                macc[yi][13] = fmaf(e, h3.y, macc[yi][13]);
                macc[yi][14] = fmaf(e, h3.z, macc[yi][14]);
                macc[yi][15] = fmaf(e, h3.w, macc[yi][15]);
            }
        }
        __syncthreads();
    }

    // rowsum reduce across the 16 tl threads per y
#pragma unroll
    for (int yi = 0; yi < 4; yi++) red[(ty*4 + yi)*16 + tl] = rsum[yi];
    __syncthreads();
    if (tid < 64) {
        float s = 0.f;
#pragma unroll
        for (int i = 0; i < 16; i++) s += red[tid*16 + i];
        rowsums[tid] = s;
    }
    __syncthreads();

    // ---------------- yhat ----------------
    // thread's f-tile: f = fi*64 + tl*4 + j  -> fw chunk index fi*16 + tl
#pragma unroll
    for (int yi = 0; yi < 4; yi++) {
        int y = ty*4 + yi;
        int gy = ybase + y;
        float p = 0.f;
        if (gy < Yy) {
            const float4* fw4 = (const float4*)(fw + (size_t)gy*Ff);
#pragma unroll
            for (int fi = 0; fi < 4; fi++) {
                float4 w = fw4[fi*16 + tl];
                p = fmaf(w.x, macc[yi][fi*4+0], p);
                p = fmaf(w.y, macc[yi][fi*4+1], p);
                p = fmaf(w.z, macc[yi][fi*4+2], p);
                p = fmaf(w.w, macc[yi][fi*4+3], p);
            }
        }
        red[y*16 + tl] = p;
    }
    __syncthreads();
    if (tid < 64) {
        int gy = ybase + tid;
        if (gy < Yy) {
            float s = 0.f;
#pragma unroll
            for (int i = 0; i < 16; i++) s += red[tid*16 + i];
            out[(size_t)b*Yy + gy] = s / rowsums[tid] + fb[gy];
        }
    }
    __syncthreads();

    // ---------------- alpha rescale: alpha = e / Z (scalar, coalesced) -------
    for (int y = 0; y < 64; y++) {
        int gy = ybase + y;
        if (gy >= Yy) break;
        float inv = 1.f / rowsums[y];
        float* row = ablk + (size_t)y*Ll;
        for (int l = tid; l < Ll; l += 256)
            row[l] *= inv;
    }
}

// ---------------------------------------------------------------------------
// K3: BCE loss, two-stage deterministic reduction
// ---------------------------------------------------------------------------
__global__ void k_loss1(const float* __restrict__ target, const float* __restrict__ out)
{
    __shared__ float red[256];
    int tid = threadIdx.x;
    float s = 0.f;
    for (int i = blockIdx.x*256 + tid; i < Bb*Yy; i += gridDim.x*256) {
        float yh = out[i];
        float t  = target[i];
        s += fmaxf(yh, 0.f) - yh*t + log1pf(__expf(-fabsf(yh)));
    }
    red[tid] = s;
    __syncthreads();
    for (int st = 128; st > 0; st >>= 1) {
        if (tid < st) red[tid] += red[tid + st];
        __syncthreads();
    }
    if (tid == 0) g_part[blockIdx.x] = red[0];
}

__global__ void k_loss2(float* __restrict__ out)
{
    __shared__ float red[128];
    int tid = threadIdx.x;
    red[tid] = (tid < 70) ? g_part[tid] : 0.f;
    __syncthreads();
    for (int st = 64; st > 0; st >>= 1) {
        if (tid < st) red[tid] += red[tid + st];
        __syncthreads();
    }
    if (tid == 0) out[Bb*Yy] = red[0] / (float)(Bb*Yy);
}

// ---------------------------------------------------------------------------
extern "C" void kernel_launch(void* const* d_in, const int* in_sizes, int n_in,
                              void* d_out, int out_size)
{
    const int*   x      = (const int*)d_in[0];
    const float* target = (const float*)d_in[1];
    const float* embW   = (const float*)d_in[2];
    const float* convw  = (const float*)d_in[3];
    const float* convb  = (const float*)d_in[4];
    const float* Uw     = (const float*)d_in[5];
    const float* fw     = (const float*)d_in[6];
    const float* fb     = (const float*)d_in[7];
    float* out = (float*)d_out;

    cudaFuncSetAttribute(k_attn, cudaFuncAttributeMaxDynamicSharedMemorySize, SM_BYTES);

    k_transpose<<<(Ff*Ee*KW + 255)/256, 256>>>(convw);
    k_conv<<<dim3(Ll/16, Bb), 256>>>(x, embW, convb);
    k_attn<<<dim3(YTILES, Bb), 256, SM_BYTES>>>(Uw, fw, fb, out);
    k_loss1<<<70, 256>>>(target, out);
    k_loss2<<<1, 128>>>(out);
}

// round 5
// speedup vs baseline: 1.5985x; 1.0025x over previous
#include <cuda_runtime.h>
#include <math.h>

// Problem constants
#define Bb    8
#define Ll    2048
#define Vv    51919
#define Ee    100
#define Ff    256
#define KW    9
#define Yy    8921
#define YTILES 140
#define US    260       // Usm row stride (floats): mult of 4 (alignment), rows+4 -> distinct bank groups

// Device scratch (no cudaMalloc allowed)
__device__ float g_wT[Ee*KW*Ff];          // conv weights transposed: [(e*K+k)][f]
__device__ float g_h[(size_t)Bb*Ll*Ff];   // conv output h: [b][l][f]
__device__ float g_part[256];             // loss partials

// ---------------------------------------------------------------------------
// K0: transpose conv_w [F,E,K] -> g_wT [(E*K), F]
// ---------------------------------------------------------------------------
__global__ void k_transpose(const float* __restrict__ w)
{
    int idx = blockIdx.x * 256 + threadIdx.x;
    if (idx < Ff*Ee*KW) {
        int f = idx / (Ee*KW);
        int r = idx - f*(Ee*KW);
        g_wT[r*Ff + f] = w[idx];
    }
}

// ---------------------------------------------------------------------------
// K1: embedding gather + conv1d(K=9, same pad) + bias + tanh -> g_h [b][l][f]
// ---------------------------------------------------------------------------
__global__ __launch_bounds__(256) void k_conv(const int* __restrict__ x,
                                              const float* __restrict__ embW,
                                              const float* __restrict__ convb)
{
    __shared__ int   toks[24];
    __shared__ float semb[24][Ee];

    int tid = threadIdx.x;
    int b   = blockIdx.y;
    int l0  = blockIdx.x * 16;

    if (tid < 24) {
        int l = l0 - 4 + tid;
        toks[tid] = (l >= 0 && l < Ll) ? x[b*Ll + l] : -1;
    }
    __syncthreads();

    for (int idx = tid; idx < 24*Ee; idx += 256) {
        int t = idx / Ee;
        int c = idx - t*Ee;
        int tok = toks[t];
        semb[t][c] = (tok >= 0) ? embW[(size_t)tok*Ee + c] : 0.f;
    }
    __syncthreads();

    int f = tid;
    float acc[16];
#pragma unroll
    for (int j = 0; j < 16; j++) acc[j] = 0.f;

    for (int e = 0; e < Ee; e++) {
        float r[24];
#pragma unroll
        for (int t = 0; t < 24; t++) r[t] = semb[t][e];
#pragma unroll
        for (int k = 0; k < KW; k++) {
            float w = g_wT[(e*KW + k)*Ff + f];
#pragma unroll
            for (int j = 0; j < 16; j++)
                acc[j] = fmaf(w, r[j + k], acc[j]);
        }
    }

    float bias = convb[f];
    float* hp = g_h + ((size_t)b*Ll + l0)*Ff + f;
#pragma unroll
    for (int j = 0; j < 16; j++)
        hp[(size_t)j*Ff] = tanhf(acc[j] + bias);
}

// ---------------------------------------------------------------------------
// K2: FUSED attention per (batch, 64-label tile), single pass over L.
//   h tile stored as XOR-swizzled float4 slots: slot(r,c4) = r*64 + (c4 ^ ((r>>2)&7))
//   -> conflict-free LDS.128 in both GEMM phases (quarter-warp wavefronts).
//   m-GEMM per-thread f-tile: f = fi*64 + tl*4 + j  (4 x float4 at chunk fi*16+tl)
// NOTE: alpha region of d_out starts at element B*Y+1 (NOT 16B-aligned)
//       -> all global accesses there are scalar (4B) but coalesced.
// ---------------------------------------------------------------------------
#define SM_FLOATS (64*US + 64*256 + 64*64 + 64*16 + 64)
#define SM_BYTES  (SM_FLOATS * 4)

__global__ __launch_bounds__(256) void k_attn(const float* __restrict__ Uw,
                                              const float* __restrict__ fw,
                                              const float* __restrict__ fb,
                                              float* __restrict__ out)
{
    extern __shared__ float sm[];
    float*  Usm     = sm;                    // [64][US]
    float4* hsm4    = (float4*)(sm + 64*US); // [64 rows][64 slots] swizzled
    float*  esm     = sm + 64*US + 64*256;   // [64][64]
    float*  red     = esm + 64*64;           // [64][16]
    float*  rowsums = red + 64*16;           // [64]

    int tid = threadIdx.x;
    int ty  = tid >> 4;       // 0..15 -> 4 y's each
    int tl  = tid & 15;       // 0..15
    int b   = blockIdx.y;
    int ybase = blockIdx.x * 64;

    // Load U tile (zero-fill beyond Y)
    for (int idx = tid; idx < 64*256; idx += 256) {
        int r = idx >> 8, c = idx & 255;
        int gy = ybase + r;
        Usm[r*US + c] = (gy < Yy) ? Uw[(size_t)gy*Ff + c] : 0.f;
    }

    float macc[4][16];
#pragma unroll
    for (int yi = 0; yi < 4; yi++)
#pragma unroll
        for (int fi = 0; fi < 16; fi++) macc[yi][fi] = 0.f;
    float rsum[4] = {0.f, 0.f, 0.f, 0.f};
    __syncthreads();

    const float* hbase = g_h + (size_t)b*Ll*Ff;
    // out layout: yhat [B*Y], loss [1], alpha [B][Y][L]
    float* alpha = out + (size_t)Bb*Yy + 1;
    float* ablk  = alpha + ((size_t)b*Yy + ybase)*Ll;

    for (int lc = 0; lc < Ll/64; lc++) {
        // load h tile [64 l][256 f] with xor swizzle on float4 slots
        const float4* hp4 = (const float4*)(hbase + (size_t)lc*64*Ff);
        for (int idx = tid; idx < 64*64; idx += 256) {
            int r = idx >> 6, c4 = idx & 63;
            hsm4[r*64 + (c4 ^ ((r >> 2) & 7))] = hp4[r*64 + c4];
        }
        __syncthreads();

        // ---- s-GEMM 4y x 4l ----
        float acc[4][4];
#pragma unroll
        for (int i = 0; i < 4; i++)
#pragma unroll
            for (int j = 0; j < 4; j++) acc[i][j] = 0.f;

#pragma unroll 4
        for (int k4 = 0; k4 < 64; k4++) {
            int sw = k4 ^ (tl & 7);     // swizzle term: (tl*4+li)>>2 == tl for li<4
            float4 bv[4];
#pragma unroll
            for (int li = 0; li < 4; li++)
                bv[li] = hsm4[(tl*4 + li)*64 + sw];
            float4 av[4];
#pragma unroll
            for (int yi = 0; yi < 4; yi++)
                av[yi] = *(const float4*)&Usm[(ty*4 + yi)*US + k4*4];
#pragma unroll
            for (int yi = 0; yi < 4; yi++)
#pragma unroll
                for (int li = 0; li < 4; li++) {
                    acc[yi][li] = fmaf(av[yi].x, bv[li].x, acc[yi][li]);
                    acc[yi][li] = fmaf(av[yi].y, bv[li].y, acc[yi][li]);
                    acc[yi][li] = fmaf(av[yi].z, bv[li].z, acc[yi][li]);
                    acc[yi][li] = fmaf(av[yi].w, bv[li].w, acc[yi][li]);
                }
        }

        // ---- e = exp(s); rowsum; stash to esm ----
#pragma unroll
        for (int yi = 0; yi < 4; yi++) {
            int y = ty*4 + yi;
            float4 ev;
            ev.x = __expf(acc[yi][0]);
            ev.y = __expf(acc[yi][1]);
            ev.z = __expf(acc[yi][2]);
            ev.w = __expf(acc[yi][3]);
            rsum[yi] += ev.x + ev.y + ev.z + ev.w;
            *(float4*)&esm[y*64 + tl*4] = ev;
        }
        __syncthreads();

        // ---- coalesced SCALAR stream of e to gmem (alpha base misaligned) ----
        for (int idx = tid; idx < 64*64; idx += 256) {
            int y = idx >> 6, l = idx & 63;
            if (ybase + y < Yy)
                ablk[(size_t)y*Ll + lc*64 + l] = esm[idx];
        }

        // ---- m-GEMM: macc[y][fi*4+j] += e[y][l] * h[l][fi*64+tl*4+j] ----
#pragma unroll 2
        for (int l = 0; l < 64; l++) {
            int x = (l >> 2) & 7;
            const float4* hrow = hsm4 + l*64;
            int t = tl ^ x;
            float4 h0 = hrow[t];
            float4 h1 = hrow[16 + t];
            float4 h2 = hrow[32 + t];
            float4 h3 = hrow[48 + t];
            float evv[4];
#pragma unroll
            for (int yi = 0; yi < 4; yi++) evv[yi] = esm[(ty*4 + yi)*64 + l];
#pragma unroll
            for (int yi = 0; yi < 4; yi++) {
                float e = evv[yi];
                macc[yi][0]  = fmaf(e, h0.x, macc[yi][0]);
                macc[yi][1]  = fmaf(e, h0.y, macc[yi][1]);
                macc[yi][2]  = fmaf(e, h0.z, macc[yi][2]);
                macc[yi][3]  = fmaf(e, h0.w, macc[yi][3]);
                macc[yi][4]  = fmaf(e, h1.x, macc[yi][4]);
                macc[yi][5]  = fmaf(e, h1.y, macc[yi][5]);
                macc[yi][6]  = fmaf(e, h1.z, macc[yi][6]);
                macc[yi][7]  = fmaf(e, h1.w, macc[yi][7]);
                macc[yi][8]  = fmaf(e, h2.x, macc[yi][8]);
                macc[yi][9]  = fmaf(e, h2.y, macc[yi][9]);
                macc[yi][10] = fmaf(e, h2.z, macc[yi][10]);
                macc[yi][11] = fmaf(e, h2.w, macc[yi][11]);
                macc[yi][12] = fmaf(e, h3.x, macc[yi][12]);
                macc[yi][13] = fmaf(e, h3.y, macc[yi][13]);
                macc[yi][14] = fmaf(e, h3.z, macc[yi][14]);
                macc[yi][15] = fmaf(e, h3.w, macc[yi][15]);
            }
        }
        __syncthreads();
    }

    // rowsum reduce across the 16 tl threads per y
#pragma unroll
    for (int yi = 0; yi < 4; yi++) red[(ty*4 + yi)*16 + tl] = rsum[yi];
    __syncthreads();
    if (tid < 64) {
        float s = 0.f;
#pragma unroll
        for (int i = 0; i < 16; i++) s += red[tid*16 + i];
        rowsums[tid] = s;
    }
    __syncthreads();

    // ---------------- yhat ----------------
    // thread's f-tile: f = fi*64 + tl*4 + j  -> fw chunk index fi*16 + tl
#pragma unroll
    for (int yi = 0; yi < 4; yi++) {
        int y = ty*4 + yi;
        int gy = ybase + y;
        float p = 0.f;
        if (gy < Yy) {
            const float4* fw4 = (const float4*)(fw + (size_t)gy*Ff);
#pragma unroll
            for (int fi = 0; fi < 4; fi++) {
                float4 w = fw4[fi*16 + tl];
                p = fmaf(w.x, macc[yi][fi*4+0], p);
                p = fmaf(w.y, macc[yi][fi*4+1], p);
                p = fmaf(w.z, macc[yi][fi*4+2], p);
                p = fmaf(w.w, macc[yi][fi*4+3], p);
            }
        }
        red[y*16 + tl] = p;
    }
    __syncthreads();
    if (tid < 64) {
        int gy = ybase + tid;
        if (gy < Yy) {
            float s = 0.f;
#pragma unroll
            for (int i = 0; i < 16; i++) s += red[tid*16 + i];
            out[(size_t)b*Yy + gy] = s / rowsums[tid] + fb[gy];
        }
    }
    __syncthreads();

    // ---------------- alpha rescale: alpha = e / Z (scalar, coalesced) -------
    for (int y = 0; y < 64; y++) {
        int gy = ybase + y;
        if (gy >= Yy) break;
        float inv = 1.f / rowsums[y];
        float* row = ablk + (size_t)y*Ll;
        for (int l = tid; l < Ll; l += 256)
            row[l] *= inv;
    }
}

// ---------------------------------------------------------------------------
// K3: BCE loss, two-stage deterministic reduction
// ---------------------------------------------------------------------------
__global__ void k_loss1(const float* __restrict__ target, const float* __restrict__ out)
{
    __shared__ float red[256];
    int tid = threadIdx.x;
    float s = 0.f;
    for (int i = blockIdx.x*256 + tid; i < Bb*Yy; i += gridDim.x*256) {
        float yh = out[i];
        float t  = target[i];
        s += fmaxf(yh, 0.f) - yh*t + log1pf(__expf(-fabsf(yh)));
    }
    red[tid] = s;
    __syncthreads();
    for (int st = 128; st > 0; st >>= 1) {
        if (tid < st) red[tid] += red[tid + st];
        __syncthreads();
    }
    if (tid == 0) g_part[blockIdx.x] = red[0];
}

__global__ void k_loss2(float* __restrict__ out)
{
    __shared__ float red[128];
    int tid = threadIdx.x;
    red[tid] = (tid < 70) ? g_part[tid] : 0.f;
    __syncthreads();
    for (int st = 64; st > 0; st >>= 1) {
        if (tid < st) red[tid] += red[tid + st];
        __syncthreads();
    }
    if (tid == 0) out[Bb*Yy] = red[0] / (float)(Bb*Yy);
}

// ---------------------------------------------------------------------------
extern "C" void kernel_launch(void* const* d_in, const int* in_sizes, int n_in,
                              void* d_out, int out_size)
{
    const int*   x      = (const int*)d_in[0];
    const float* target = (const float*)d_in[1];
    const float* embW   = (const float*)d_in[2];
    const float* convw  = (const float*)d_in[3];
    const float* convb  = (const float*)d_in[4];
    const float* Uw     = (const float*)d_in[5];
    const float* fw     = (const float*)d_in[6];
    const float* fb     = (const float*)d_in[7];
    float* out = (float*)d_out;

    cudaFuncSetAttribute(k_attn, cudaFuncAttributeMaxDynamicSharedMemorySize, SM_BYTES);

    k_transpose<<<(Ff*Ee*KW + 255)/256, 256>>>(convw);
    k_conv<<<dim3(Ll/16, Bb), 256>>>(x, embW, convb);
    k_attn<<<dim3(YTILES, Bb), 256, SM_BYTES>>>(Uw, fw, fb, out);
    k_loss1<<<70, 256>>>(target, out);
    k_loss2<<<1, 128>>>(out);
}

// round 6
// speedup vs baseline: 2.5012x; 1.5647x over previous
#include <cuda_runtime.h>
#include <math.h>

// Problem constants
#define Bb    8
#define Ll    2048
#define Vv    51919
#define Ee    100
#define Ff    256
#define KW    9
#define Yy    8921
#define YTILES 140
#define US    260       // Usm row stride (floats): mult of 4 (alignment), rows+4 -> distinct bank groups

// Device scratch (no cudaMalloc allowed)
__device__ float g_wT[Ee*KW*Ff];          // conv weights transposed: [(e*K+k)][f]
__device__ float g_h[(size_t)Bb*Ll*Ff];   // conv output h: [b][l][f]
__device__ float g_part[256];             // loss partials

// ---------------------------------------------------------------------------
// K0: transpose conv_w [F,E,K] -> g_wT [(E*K), F]
// ---------------------------------------------------------------------------
__global__ void k_transpose(const float* __restrict__ w)
{
    int idx = blockIdx.x * 256 + threadIdx.x;
    if (idx < Ff*Ee*KW) {
        int f = idx / (Ee*KW);
        int r = idx - f*(Ee*KW);
        g_wT[r*Ff + f] = w[idx];
    }
}

// ---------------------------------------------------------------------------
// K1: embedding gather + conv1d(K=9, same pad) + bias + tanh -> g_h [b][l][f]
// ---------------------------------------------------------------------------
__global__ __launch_bounds__(256) void k_conv(const int* __restrict__ x,
                                              const float* __restrict__ embW,
                                              const float* __restrict__ convb)
{
    __shared__ int   toks[24];
    __shared__ float semb[24][Ee];

    int tid = threadIdx.x;
    int b   = blockIdx.y;
    int l0  = blockIdx.x * 16;

    if (tid < 24) {
        int l = l0 - 4 + tid;
        toks[tid] = (l >= 0 && l < Ll) ? x[b*Ll + l] : -1;
    }
    __syncthreads();

    for (int idx = tid; idx < 24*Ee; idx += 256) {
        int t = idx / Ee;
        int c = idx - t*Ee;
        int tok = toks[t];
        semb[t][c] = (tok >= 0) ? embW[(size_t)tok*Ee + c] : 0.f;
    }
    __syncthreads();

    int f = tid;
    float acc[16];
#pragma unroll
    for (int j = 0; j < 16; j++) acc[j] = 0.f;

    for (int e = 0; e < Ee; e++) {
        float r[24];
#pragma unroll
        for (int t = 0; t < 24; t++) r[t] = semb[t][e];
#pragma unroll
        for (int k = 0; k < KW; k++) {
            float w = g_wT[(e*KW + k)*Ff + f];
#pragma unroll
            for (int j = 0; j < 16; j++)
                acc[j] = fmaf(w, r[j + k], acc[j]);
        }
    }

    float bias = convb[f];
    float* hp = g_h + ((size_t)b*Ll + l0)*Ff + f;
#pragma unroll
    for (int j = 0; j < 16; j++)
        hp[(size_t)j*Ff] = tanhf(acc[j] + bias);
}

// ---------------------------------------------------------------------------
// K2: FUSED attention per (batch, 64-label tile), single pass over L.
//   h tile stored as XOR-swizzled float4 slots: slot(r,c4) = r*64 + (c4 ^ ((r>>2)&7))
//   -> conflict-free LDS.128 in both GEMM phases (quarter-warp wavefronts).
//   m-GEMM per-thread f-tile: f = fi*64 + tl*4 + j  (4 x float4 at chunk fi*16+tl)
// NOTE: alpha region of d_out starts at element B*Y+1 (NOT 16B-aligned)
//       -> all global accesses there are scalar (4B) but coalesced.
// ---------------------------------------------------------------------------
#define SM_FLOATS (64*US + 64*256 + 64*64 + 64*16 + 64)
#define SM_BYTES  (SM_FLOATS * 4)

__global__ __launch_bounds__(256) void k_attn(const float* __restrict__ Uw,
                                              const float* __restrict__ fw,
                                              const float* __restrict__ fb,
                                              float* __restrict__ out)
{
    extern __shared__ float sm[];
    float*  Usm     = sm;                    // [64][US]
    float4* hsm4    = (float4*)(sm + 64*US); // [64 rows][64 slots] swizzled
    float*  esm     = sm + 64*US + 64*256;   // [64][64]
    float*  red     = esm + 64*64;           // [64][16]
    float*  rowsums = red + 64*16;           // [64]

    int tid = threadIdx.x;
    int ty  = tid >> 4;       // 0..15 -> 4 y's each
    int tl  = tid & 15;       // 0..15
    int b   = blockIdx.y;
    int ybase = blockIdx.x * 64;

    // Load U tile (zero-fill beyond Y)
    for (int idx = tid; idx < 64*256; idx += 256) {
        int r = idx >> 8, c = idx & 255;
        int gy = ybase + r;
        Usm[r*US + c] = (gy < Yy) ? Uw[(size_t)gy*Ff + c] : 0.f;
    }

    float macc[4][16];
#pragma unroll
    for (int yi = 0; yi < 4; yi++)
#pragma unroll
        for (int fi = 0; fi < 16; fi++) macc[yi][fi] = 0.f;
    float rsum[4] = {0.f, 0.f, 0.f, 0.f};
    __syncthreads();

    const float* hbase = g_h + (size_t)b*Ll*Ff;
    // out layout: yhat [B*Y], loss [1], alpha [B][Y][L]
    float* alpha = out + (size_t)Bb*Yy + 1;
    float* ablk  = alpha + ((size_t)b*Yy + ybase)*Ll;

    for (int lc = 0; lc < Ll/64; lc++) {
        // load h tile [64 l][256 f] with xor swizzle on float4 slots
        const float4* hp4 = (const float4*)(hbase + (size_t)lc*64*Ff);
        for (int idx = tid; idx < 64*64; idx += 256) {
            int r = idx >> 6, c4 = idx & 63;
            hsm4[r*64 + (c4 ^ ((r >> 2) & 7))] = hp4[r*64 + c4];
        }
        __syncthreads();

        // ---- s-GEMM 4y x 4l ----
        float acc[4][4];
#pragma unroll
        for (int i = 0; i < 4; i++)
#pragma unroll
            for (int j = 0; j < 4; j++) acc[i][j] = 0.f;

#pragma unroll 4
        for (int k4 = 0; k4 < 64; k4++) {
            int sw = k4 ^ (tl & 7);     // swizzle term: (tl*4+li)>>2 == tl for li<4
            float4 bv[4];
#pragma unroll
            for (int li = 0; li < 4; li++)
                bv[li] = hsm4[(tl*4 + li)*64 + sw];
            float4 av[4];
#pragma unroll
            for (int yi = 0; yi < 4; yi++)
                av[yi] = *(const float4*)&Usm[(ty*4 + yi)*US + k4*4];
#pragma unroll
            for (int yi = 0; yi < 4; yi++)
#pragma unroll
                for (int li = 0; li < 4; li++) {
                    acc[yi][li] = fmaf(av[yi].x, bv[li].x, acc[yi][li]);
                    acc[yi][li] = fmaf(av[yi].y, bv[li].y, acc[yi][li]);
                    acc[yi][li] = fmaf(av[yi].z, bv[li].z, acc[yi][li]);
                    acc[yi][li] = fmaf(av[yi].w, bv[li].w, acc[yi][li]);
                }
        }

        // ---- e = exp(s); rowsum; stash to esm ----
#pragma unroll
        for (int yi = 0; yi < 4; yi++) {
            int y = ty*4 + yi;
            float4 ev;
            ev.x = __expf(acc[yi][0]);
            ev.y = __expf(acc[yi][1]);
            ev.z = __expf(acc[yi][2]);
            ev.w = __expf(acc[yi][3]);
            rsum[yi] += ev.x + ev.y + ev.z + ev.w;
            *(float4*)&esm[y*64 + tl*4] = ev;
        }
        __syncthreads();

        // ---- coalesced SCALAR stream of e to gmem (alpha base misaligned) ----
        for (int idx = tid; idx < 64*64; idx += 256) {
            int y = idx >> 6, l = idx & 63;
            if (ybase + y < Yy)
                ablk[(size_t)y*Ll + lc*64 + l] = esm[idx];
        }

        // ---- m-GEMM: macc[y][fi*4+j] += e[y][l] * h[l][fi*64+tl*4+j] ----
#pragma unroll 2
        for (int l = 0; l < 64; l++) {
            int x = (l >> 2) & 7;
            const float4* hrow = hsm4 + l*64;
            int t = tl ^ x;
            float4 h0 = hrow[t];
            float4 h1 = hrow[16 + t];
            float4 h2 = hrow[32 + t];
            float4 h3 = hrow[48 + t];
            float evv[4];
#pragma unroll
            for (int yi = 0; yi < 4; yi++) evv[yi] = esm[(ty*4 + yi)*64 + l];
#pragma unroll
            for (int yi = 0; yi < 4; yi++) {
                float e = evv[yi];
                macc[yi][0]  = fmaf(e, h0.x, macc[yi][0]);
                macc[yi][1]  = fmaf(e, h0.y, macc[yi][1]);
                macc[yi][2]  = fmaf(e, h0.z, macc[yi][2]);
                macc[yi][3]  = fmaf(e, h0.w, macc[yi][3]);
                macc[yi][4]  = fmaf(e, h1.x, macc[yi][4]);
                macc[yi][5]  = fmaf(e, h1.y, macc[yi][5]);
                macc[yi][6]  = fmaf(e, h1.z, macc[yi][6]);
                macc[yi][7]  = fmaf(e, h1.w, macc[yi][7]);
                macc[yi][8]  = fmaf(e, h2.x, macc[yi][8]);
                macc[yi][9]  = fmaf(e, h2.y, macc[yi][9]);
                macc[yi][10] = fmaf(e, h2.z, macc[yi][10]);
                macc[yi][11] = fmaf(e, h2.w, macc[yi][11]);
                macc[yi][12] = fmaf(e, h3.x, macc[yi][12]);
                macc[yi][13] = fmaf(e, h3.y, macc[yi][13]);
                macc[yi][14] = fmaf(e, h3.z, macc[yi][14]);
                macc[yi][15] = fmaf(e, h3.w, macc[yi][15]);
            }
        }
        __syncthreads();
    }

    // rowsum reduce across the 16 tl threads per y
#pragma unroll
    for (int yi = 0; yi < 4; yi++) red[(ty*4 + yi)*16 + tl] = rsum[yi];
    __syncthreads();
    if (tid < 64) {
        float s = 0.f;
#pragma unroll
        for (int i = 0; i < 16; i++) s += red[tid*16 + i];
        rowsums[tid] = s;
    }
    __syncthreads();

    // ---------------- yhat ----------------
    // thread's f-tile: f = fi*64 + tl*4 + j  -> fw chunk index fi*16 + tl
#pragma unroll
    for (int yi = 0; yi < 4; yi++) {
        int y = ty*4 + yi;
        int gy = ybase + y;
        float p = 0.f;
        if (gy < Yy) {
            const float4* fw4 = (const float4*)(fw + (size_t)gy*Ff);
#pragma unroll
            for (int fi = 0; fi < 4; fi++) {
                float4 w = fw4[fi*16 + tl];
                p = fmaf(w.x, macc[yi][fi*4+0], p);
                p = fmaf(w.y, macc[yi][fi*4+1], p);
                p = fmaf(w.z, macc[yi][fi*4+2], p);
                p = fmaf(w.w, macc[yi][fi*4+3], p);
            }
        }
        red[y*16 + tl] = p;
    }
    __syncthreads();
    if (tid < 64) {
        int gy = ybase + tid;
        if (gy < Yy) {
            float s = 0.f;
#pragma unroll
            for (int i = 0; i < 16; i++) s += red[tid*16 + i];
            out[(size_t)b*Yy + gy] = s / rowsums[tid] + fb[gy];
        }
    }
    __syncthreads();

    // ---------------- alpha rescale: alpha = e / Z (scalar, coalesced) -------
    for (int y = 0; y < 64; y++) {
        int gy = ybase + y;
        if (gy >= Yy) break;
        float inv = 1.f / rowsums[y];
        float* row = ablk + (size_t)y*Ll;
        for (int l = tid; l < Ll; l += 256)
            row[l] *= inv;
    }
}

// ---------------------------------------------------------------------------
// K3: BCE loss, two-stage deterministic reduction
// ---------------------------------------------------------------------------
__global__ void k_loss1(const float* __restrict__ target, const float* __restrict__ out)
{
    __shared__ float red[256];
    int tid = threadIdx.x;
    float s = 0.f;
    for (int i = blockIdx.x*256 + tid; i < Bb*Yy; i += gridDim.x*256) {
        float yh = out[i];
        float t  = target[i];
        s += fmaxf(yh, 0.f) - yh*t + log1pf(__expf(-fabsf(yh)));
    }
    red[tid] = s;
    __syncthreads();
    for (int st = 128; st > 0; st >>= 1) {
        if (tid < st) red[tid] += red[tid + st];
        __syncthreads();
    }
    if (tid == 0) g_part[blockIdx.x] = red[0];
}

__global__ void k_loss2(float* __restrict__ out)
{
    __shared__ float red[128];
    int tid = threadIdx.x;
    red[tid] = (tid < 70) ? g_part[tid] : 0.f;
    __syncthreads();
    for (int st = 64; st > 0; st >>= 1) {
        if (tid < st) red[tid] += red[tid + st];
        __syncthreads();
    }
    if (tid == 0) out[Bb*Yy] = red[0] / (float)(Bb*Yy);
}

// ---------------------------------------------------------------------------
extern "C" void kernel_launch(void* const* d_in, const int* in_sizes, int n_in,
                              void* d_out, int out_size)
{
    const int*   x      = (const int*)d_in[0];
    const float* target = (const float*)d_in[1];
    const float* embW   = (const float*)d_in[2];
    const float* convw  = (const float*)d_in[3];
    const float* convb  = (const float*)d_in[4];
    const float* Uw     = (const float*)d_in[5];
    const float* fw     = (const float*)d_in[6];
    const float* fb     = (const float*)d_in[7];
    float* out = (float*)d_out;

    cudaFuncSetAttribute(k_attn, cudaFuncAttributeMaxDynamicSharedMemorySize, SM_BYTES);

    k_transpose<<<(Ff*Ee*KW + 255)/256, 256>>>(convw);
    k_conv<<<dim3(Ll/16, Bb), 256>>>(x, embW, convb);
    k_attn<<<dim3(YTILES, Bb), 256, SM_BYTES>>>(Uw, fw, fb, out);
    k_loss1<<<70, 256>>>(target, out);
    k_loss2<<<1, 128>>>(out);
}